// round 10
// baseline (speedup 1.0000x reference)
#include <cuda_runtime.h>
#include <cuda_bf16.h>
#include <math.h>
#include <stdint.h>

#define TT 256
#define BB 64
#define DD 1024
#define HH 2048

#define GRID 256
#define SCTHREADS 256
#define NBD 16           // n-blocks (each 128 wide)
#define KBD 16           // k-blocks (each 128 deep)
#define NSL 128
#define KSL 128
#define STEP_ELEMS (BB * HH)   // 131072

typedef unsigned long long ull;

// Scratch (no cudaMalloc allowed)
__device__ __align__(16) float g_xproj[(size_t)TT * BB * HH];     // 128 MB
__device__ __align__(16) float g_part[(size_t)KBD * BB * HH];     // 8 MB
__device__ __align__(16) __nv_bfloat16 g_xhi[(size_t)TT * BB * DD];
__device__ __align__(16) __nv_bfloat16 g_xlo[(size_t)TT * BB * DD];
__device__ __align__(16) __nv_bfloat16 g_whi[(size_t)DD * HH];
__device__ __align__(16) __nv_bfloat16 g_wlo[(size_t)DD * HH];
__device__ unsigned g_count;     // monotonic arrival counter (zeroed per launch)

__device__ __forceinline__ uint32_t smem_to_u32(const void* p) {
    uint32_t a;
    asm("{ .reg .u64 t; cvta.to.shared.u64 t, %1; cvt.u32.u64 %0, t; }"
        : "=r"(a) : "l"(p));
    return a;
}

// ---- mma.sync helpers (sm_80-era PTX, compiles for compute_103) --------------
__device__ __forceinline__ void ldsm_x4(uint32_t addr, uint32_t* r) {
    asm volatile("ldmatrix.sync.aligned.m8n8.x4.shared.b16 {%0,%1,%2,%3}, [%4];"
                 : "=r"(r[0]), "=r"(r[1]), "=r"(r[2]), "=r"(r[3]) : "r"(addr));
}
__device__ __forceinline__ void ldsm_x4_t(uint32_t addr, uint32_t* r) {
    asm volatile("ldmatrix.sync.aligned.m8n8.x4.trans.shared.b16 {%0,%1,%2,%3}, [%4];"
                 : "=r"(r[0]), "=r"(r[1]), "=r"(r[2]), "=r"(r[3]) : "r"(addr));
}
__device__ __forceinline__ void mma_bf16(float* c, const uint32_t* a,
                                         uint32_t b0, uint32_t b1) {
    asm volatile(
        "mma.sync.aligned.m16n8k16.row.col.f32.bf16.bf16.f32 "
        "{%0,%1,%2,%3}, {%4,%5,%6,%7}, {%8,%9}, {%0,%1,%2,%3};"
        : "+f"(c[0]), "+f"(c[1]), "+f"(c[2]), "+f"(c[3])
        : "r"(a[0]), "r"(a[1]), "r"(a[2]), "r"(a[3]), "r"(b0), "r"(b1));
}

// hi/lo split of 4 floats into packed bf16x2 pairs
__device__ __forceinline__ void split4(const float4& v, uint2& hi, uint2& lo) {
    float s[4] = {v.x, v.y, v.z, v.w};
    __nv_bfloat16 h[4], l[4];
#pragma unroll
    for (int j = 0; j < 4; j++) {
        h[j] = __float2bfloat16(s[j]);
        l[j] = __float2bfloat16(s[j] - __bfloat162float(h[j]));
    }
    __nv_bfloat162 h01 = __halves2bfloat162(h[0], h[1]);
    __nv_bfloat162 h23 = __halves2bfloat162(h[2], h[3]);
    __nv_bfloat162 l01 = __halves2bfloat162(l[0], l[1]);
    __nv_bfloat162 l23 = __halves2bfloat162(l[2], l[3]);
    hi = make_uint2(*(uint32_t*)&h01, *(uint32_t*)&h23);
    lo = make_uint2(*(uint32_t*)&l01, *(uint32_t*)&l23);
}

// ---- fast grid barrier: red-arrive + spin on monotonic counter ---------------
__device__ __forceinline__ void grid_barrier(unsigned& target) {
    __syncthreads();
    if (threadIdx.x == 0) {
        __threadfence();
        asm volatile("red.global.gpu.add.u32 [%0], 1;"
                     :: "l"(&g_count) : "memory");
        target += GRID;
        unsigned v;
        do {
            asm volatile("ld.acquire.gpu.u32 %0, [%1];" : "=r"(v) : "l"(&g_count));
        } while ((int)(v - target) < 0);
        __threadfence();
    }
    __syncthreads();
}

__global__ void init_kernel() { g_count = 0u; }

extern __shared__ float smem[];

// -----------------------------------------------------------------------------
// Persistent tensor-core scan, 2 CTAs/SM: all 256 steps in one launch.
// CTA (nb, kb): resident bf16 hi/lo of W_hh[kb*128:+128, nb*128:+128] in SMEM.
// Per step: convert h slice -> SMEM hi/lo; 3-term bf16-split mma to [64x128]
// fp32 partial -> g_part[kb]; barrier; distributed 16-way reduce + xproj + tanh.
// -----------------------------------------------------------------------------
#define BP 136      // bf16 per W smem row (272 B; 272 % 128 == 16, conflict-free)
#define AP 136      // bf16 per h smem row
#define SB_HI 0
#define SB_LO (SB_HI + KSL * BP * 2)          // 34816
#define SA_HI (SB_LO + KSL * BP * 2)          // 69632
#define SA_LO (SA_HI + BB * AP * 2)           // 87040
#define SC_SMEM (SA_LO + BB * AP * 2)         // 104448 bytes (x2 = 209KB/SM)

__global__ void __launch_bounds__(SCTHREADS, 2) scan_kernel(
    const float* __restrict__ state,
    const float* __restrict__ W,
    float* __restrict__ out)
{
    char* sm = (char*)smem;
    __nv_bfloat16* sbh = (__nv_bfloat16*)(sm + SB_HI);
    __nv_bfloat16* sbl = (__nv_bfloat16*)(sm + SB_LO);
    __nv_bfloat16* sah = (__nv_bfloat16*)(sm + SA_HI);
    __nv_bfloat16* sal = (__nv_bfloat16*)(sm + SA_LO);

    const int tid = threadIdx.x;
    const int cta = blockIdx.x;
    const int nb = cta & (NBD - 1);
    const int kb = cta >> 4;
    const int nbase = nb * NSL;
    const int k0 = kb * KSL;
    const int wid = tid >> 5;
    const int lane = tid & 31;
    const int wn = wid * 16;          // warp's 16-col n slice
    const int lrow = lane & 15;
    const int lcolq = lane >> 4;      // 0 or 1

    const uint32_t sbh_b = smem_to_u32(sbh);
    const uint32_t sbl_b = smem_to_u32(sbl);
    const uint32_t sah_b = smem_to_u32(sah);
    const uint32_t sal_b = smem_to_u32(sal);

    // ---- load + split resident W slice [128k x 128n] (once) ----
#pragma unroll
    for (int i = 0; i < 16; i++) {
        int idx = i * SCTHREADS + tid;      // 0..4095 float4
        int k = idx >> 5;
        int n4 = (idx & 31) * 4;
        float4 w = *(const float4*)&W[(size_t)(k0 + k) * HH + nbase + n4];
        uint2 hi, lo;
        split4(w, hi, lo);
        *(uint2*)&sbh[k * BP + n4] = hi;
        *(uint2*)&sbl[k * BP + n4] = lo;
    }
    __syncthreads();

    unsigned target = 0;

    // epilogue mapping: 256*256 threads == 65536 float2 slots exactly
    const int g = cta * SCTHREADS + tid;
    const int em = g >> 10;                 // HH/2 = 1024 float2 per row
    const int ec2 = (g & 1023) * 2;
    const size_t eoff = (size_t)em * HH + ec2;

    for (int t = 0; t < TT; t++) {
        const float* hp = (t == 0) ? state : (out + (size_t)(t - 1) * STEP_ELEMS);

        // ---- stage h slice [64m x 128k] -> bf16 hi/lo SMEM ----
#pragma unroll
        for (int i = 0; i < 8; i++) {
            int idx = i * SCTHREADS + tid;  // 0..2047 float4
            int m = idx >> 5;
            int k4 = (idx & 31) * 4;
            float4 h = __ldcg((const float4*)&hp[(size_t)m * HH + k0 + k4]);
            uint2 hi, lo;
            split4(h, hi, lo);
            *(uint2*)&sah[m * AP + k4] = hi;
            *(uint2*)&sal[m * AP + k4] = lo;
        }
        __syncthreads();

        // ---- mma mainloop: 8 k16 steps over the 128k slice ----
        float c[4][2][4];
#pragma unroll
        for (int mi = 0; mi < 4; mi++)
#pragma unroll
            for (int j = 0; j < 2; j++)
#pragma unroll
                for (int q = 0; q < 4; q++) c[mi][j][q] = 0.0f;

#pragma unroll
        for (int ks = 0; ks < 8; ks++) {
            uint32_t ah[4][4], al[4][4];
#pragma unroll
            for (int mi = 0; mi < 4; mi++) {
                uint32_t off = (uint32_t)((mi * 16 + lrow) * AP +
                                          ks * 16 + lcolq * 8) * 2;
                ldsm_x4(sah_b + off, ah[mi]);
                ldsm_x4(sal_b + off, al[mi]);
            }
            uint32_t bh[4], bl[4];
            {
                uint32_t off = (uint32_t)((ks * 16 + lrow) * BP +
                                          wn + lcolq * 8) * 2;
                ldsm_x4_t(sbh_b + off, bh);
                ldsm_x4_t(sbl_b + off, bl);
            }
#pragma unroll
            for (int mi = 0; mi < 4; mi++) {
#pragma unroll
                for (int j = 0; j < 2; j++) {
                    const int pr = j * 2;
                    mma_bf16(c[mi][j], ah[mi], bh[pr], bh[pr + 1]);
                    mma_bf16(c[mi][j], ah[mi], bl[pr], bl[pr + 1]);
                    mma_bf16(c[mi][j], al[mi], bh[pr], bh[pr + 1]);
                }
            }
        }

        // ---- write partial [64 x 128] to g_part[kb] ----
        float* P = g_part + (size_t)kb * STEP_ELEMS;
#pragma unroll
        for (int mi = 0; mi < 4; mi++) {
            const int row0 = mi * 16 + (lane >> 2);
#pragma unroll
            for (int j = 0; j < 2; j++) {
                const int col = nbase + wn + j * 8 + (lane & 3) * 2;
                *(float2*)&P[(size_t)row0 * HH + col] =
                    make_float2(c[mi][j][0], c[mi][j][1]);
                *(float2*)&P[(size_t)(row0 + 8) * HH + col] =
                    make_float2(c[mi][j][2], c[mi][j][3]);
            }
        }
        grid_barrier(target);

        // ---- distributed epilogue: reduce 16 partials + xproj, tanh ----
        {
            float2 s = *(const float2*)&g_part[eoff];
#pragma unroll
            for (int k2 = 1; k2 < KBD; k2++) {
                float2 p = *(const float2*)&g_part[(size_t)k2 * STEP_ELEMS + eoff];
                s.x += p.x; s.y += p.y;
            }
            const float2 xv = *(const float2*)&g_xproj[(size_t)t * STEP_ELEMS + eoff];
            float2 r;
            r.x = tanhf(s.x + xv.x);
            r.y = tanhf(s.y + xv.y);
            *(float2*)&out[(size_t)t * STEP_ELEMS + eoff] = r;
            if (t == TT - 1)
                *(float2*)&out[(size_t)TT * STEP_ELEMS + eoff] = r;   // final_state
        }
        grid_barrier(target);
    }
}

// -----------------------------------------------------------------------------
// Elementwise bf16 hi/lo split: hi = bf16(x), lo = bf16(x - hi)
// -----------------------------------------------------------------------------
__global__ void __launch_bounds__(256) convert_split(
    const float* __restrict__ src,
    __nv_bfloat16* __restrict__ hi,
    __nv_bfloat16* __restrict__ lo)
{
    const int i = blockIdx.x * 256 + threadIdx.x;
    float4 v = ((const float4*)src)[i];
    uint2 h, l;
    split4(v, h, l);
    ((uint2*)hi)[i] = h;
    ((uint2*)lo)[i] = l;
}

// -----------------------------------------------------------------------------
// x_proj via mma.sync bf16-split (validated R6-R8 kernel, unchanged)
// -----------------------------------------------------------------------------
#define APAD 40    // bf16 per A smem row (80 B, conflict-free ldmatrix)
#define BPAD 136   // bf16 per B smem row (272 B, conflict-free ldmatrix)

__global__ void __launch_bounds__(256) xproj_mma(
    const __nv_bfloat16* __restrict__ Xhi,
    const __nv_bfloat16* __restrict__ Xlo,
    const __nv_bfloat16* __restrict__ Whi,
    const __nv_bfloat16* __restrict__ Wlo,
    const float* __restrict__ bias)
{
    __shared__ __align__(16) __nv_bfloat16 sa[2][128 * APAD];   // hi, lo
    __shared__ __align__(16) __nv_bfloat16 sb[2][32 * BPAD];

    const int tid = threadIdx.x;
    const int wid = tid >> 5;
    const int lane = tid & 31;
    const int nbase = blockIdx.x * 128;
    const int mbase = blockIdx.y * 128;
    const int wm = (wid & 1) * 64;
    const int wn = (wid >> 1) * 32;

    float c[4][4][4];
#pragma unroll
    for (int mi = 0; mi < 4; mi++)
#pragma unroll
        for (int j = 0; j < 4; j++)
#pragma unroll
            for (int q = 0; q < 4; q++) c[mi][j][q] = 0.0f;

    uint4 pa[2][2], pb[2][2];
    const __nv_bfloat16* Xs[2] = {Xhi, Xlo};
    const __nv_bfloat16* Ws[2] = {Whi, Wlo};

#pragma unroll
    for (int v = 0; v < 2; v++) {
#pragma unroll
        for (int it = 0; it < 2; it++) {
            int idx = it * 256 + tid;
            int r = idx >> 2, c8 = (idx & 3) * 8;
            pa[v][it] = *(const uint4*)&Xs[v][(size_t)(mbase + r) * DD + c8];
            int kr = idx >> 4, n8 = (idx & 15) * 8;
            pb[v][it] = *(const uint4*)&Ws[v][(size_t)kr * HH + nbase + n8];
        }
    }

    const int lrow = lane & 15;
    const int lcolq = lane >> 4;

    for (int ch = 0; ch < DD / 32; ch++) {
#pragma unroll
        for (int v = 0; v < 2; v++) {
#pragma unroll
            for (int it = 0; it < 2; it++) {
                int idx = it * 256 + tid;
                int r = idx >> 2, c8 = (idx & 3) * 8;
                *(uint4*)&sa[v][r * APAD + c8] = pa[v][it];
                int kr = idx >> 4, n8 = (idx & 15) * 8;
                *(uint4*)&sb[v][kr * BPAD + n8] = pb[v][it];
            }
        }
        __syncthreads();
        if (ch + 1 < DD / 32) {
            const int kc = (ch + 1) * 32;
#pragma unroll
            for (int v = 0; v < 2; v++) {
#pragma unroll
                for (int it = 0; it < 2; it++) {
                    int idx = it * 256 + tid;
                    int r = idx >> 2, c8 = (idx & 3) * 8;
                    pa[v][it] = *(const uint4*)&Xs[v][(size_t)(mbase + r) * DD + kc + c8];
                    int kr = idx >> 4, n8 = (idx & 15) * 8;
                    pb[v][it] = *(const uint4*)&Ws[v][(size_t)(kc + kr) * HH + nbase + n8];
                }
            }
        }

#pragma unroll
        for (int ks = 0; ks < 2; ks++) {
            uint32_t ah[4][4], al[4][4];
#pragma unroll
            for (int mi = 0; mi < 4; mi++) {
                uint32_t off = (uint32_t)((wm + mi * 16 + lrow) * APAD +
                                          ks * 16 + lcolq * 8) * 2;
                ldsm_x4(smem_to_u32(&sa[0][0]) + off, ah[mi]);
                ldsm_x4(smem_to_u32(&sa[1][0]) + off, al[mi]);
            }
            uint32_t bh[2][4], bl[2][4];
#pragma unroll
            for (int np = 0; np < 2; np++) {
                uint32_t off = (uint32_t)((ks * 16 + lrow) * BPAD +
                                          wn + np * 16 + lcolq * 8) * 2;
                ldsm_x4_t(smem_to_u32(&sb[0][0]) + off, bh[np]);
                ldsm_x4_t(smem_to_u32(&sb[1][0]) + off, bl[np]);
            }
#pragma unroll
            for (int mi = 0; mi < 4; mi++) {
#pragma unroll
                for (int j = 0; j < 4; j++) {
                    const int np = j >> 1, pr = (j & 1) * 2;
                    mma_bf16(c[mi][j], ah[mi], bh[np][pr], bh[np][pr + 1]);
                    mma_bf16(c[mi][j], ah[mi], bl[np][pr], bl[np][pr + 1]);
                    mma_bf16(c[mi][j], al[mi], bh[np][pr], bh[np][pr + 1]);
                }
            }
        }
        __syncthreads();
    }

#pragma unroll
    for (int mi = 0; mi < 4; mi++) {
        const int row0 = mbase + wm + mi * 16 + (lane >> 2);
#pragma unroll
        for (int j = 0; j < 4; j++) {
            const int col = nbase + wn + j * 8 + (lane & 3) * 2;
            const float b0 = __ldg(&bias[col]);
            const float b1 = __ldg(&bias[col + 1]);
            float2 v0 = make_float2(c[mi][j][0] + b0, c[mi][j][1] + b1);
            float2 v1 = make_float2(c[mi][j][2] + b0, c[mi][j][3] + b1);
            *(float2*)&g_xproj[(size_t)row0 * HH + col] = v0;
            *(float2*)&g_xproj[(size_t)(row0 + 8) * HH + col] = v1;
        }
    }
}

extern "C" void kernel_launch(void* const* d_in, const int* in_sizes, int n_in,
                              void* d_out, int out_size)
{
    (void)in_sizes; (void)n_in; (void)out_size;
    const float* inputs = (const float*)d_in[0];   // [T,B,D]
    const float* state  = (const float*)d_in[1];   // [B,H]
    const float* W_xh   = (const float*)d_in[2];   // [D,H]
    const float* W_hh   = (const float*)d_in[3];   // [H,H]
    const float* b_h    = (const float*)d_in[4];   // [H]
    float* out = (float*)d_out;   // outputs [T,B,H] then final_state [B,H]

    cudaFuncSetAttribute(scan_kernel, cudaFuncAttributeMaxDynamicSharedMemorySize,
                         SC_SMEM);

    __nv_bfloat16 *xhi, *xlo, *whi, *wlo;
    cudaGetSymbolAddress((void**)&xhi, g_xhi);
    cudaGetSymbolAddress((void**)&xlo, g_xlo);
    cudaGetSymbolAddress((void**)&whi, g_whi);
    cudaGetSymbolAddress((void**)&wlo, g_wlo);

    // 0) reset barrier counter (deterministic across graph replays)
    init_kernel<<<1, 1>>>();

    // 1) bf16 hi/lo splits of X and W_xh
    convert_split<<<(TT * BB * DD / 4) / 256, 256>>>(inputs, xhi, xlo);
    convert_split<<<(DD * HH / 4) / 256, 256>>>(W_xh, whi, wlo);

    // 2) x_proj via tensor cores (mma.sync bf16-split)
    xproj_mma<<<dim3(HH / 128, (TT * BB) / 128), 256>>>(xhi, xlo, whi, wlo, b_h);

    // 3) persistent tensor-core scan, 2 CTAs/SM
    scan_kernel<<<GRID, SCTHREADS, SC_SMEM>>>(state, W_hh, out);
}

// round 11
// speedup vs baseline: 1.1081x; 1.1081x over previous
#include <cuda_runtime.h>
#include <cuda_bf16.h>
#include <math.h>
#include <stdint.h>

#define TT 256
#define BB 64
#define DD 1024
#define HH 2048

#define GRID 128
#define SCTHREADS 256
#define NBD 8            // n-blocks (each 256 wide)
#define KBD 16           // k-blocks (each 128 deep)
#define NSL 256
#define KSL 128
#define STEP_ELEMS (BB * HH)   // 131072

typedef unsigned long long ull;

// Scratch (no cudaMalloc allowed)
__device__ __align__(16) float g_xproj[(size_t)TT * BB * HH];     // 128 MB
__device__ __align__(16) float g_part[(size_t)KBD * BB * HH];     // 8 MB
__device__ __align__(16) __nv_bfloat16 g_xhi[(size_t)TT * BB * DD];
__device__ __align__(16) __nv_bfloat16 g_xlo[(size_t)TT * BB * DD];
__device__ __align__(16) __nv_bfloat16 g_whi[(size_t)DD * HH];
__device__ __align__(16) __nv_bfloat16 g_wlo[(size_t)DD * HH];
__device__ unsigned g_count;     // monotonic arrival counter (zeroed per launch)

__device__ __forceinline__ uint32_t smem_to_u32(const void* p) {
    uint32_t a;
    asm("{ .reg .u64 t; cvta.to.shared.u64 t, %1; cvt.u32.u64 %0, t; }"
        : "=r"(a) : "l"(p));
    return a;
}

// ---- mma.sync / cp.async helpers (sm_80-era PTX, fine at compute_103) --------
__device__ __forceinline__ void ldsm_x4(uint32_t addr, uint32_t* r) {
    asm volatile("ldmatrix.sync.aligned.m8n8.x4.shared.b16 {%0,%1,%2,%3}, [%4];"
                 : "=r"(r[0]), "=r"(r[1]), "=r"(r[2]), "=r"(r[3]) : "r"(addr));
}
__device__ __forceinline__ void ldsm_x4_t(uint32_t addr, uint32_t* r) {
    asm volatile("ldmatrix.sync.aligned.m8n8.x4.trans.shared.b16 {%0,%1,%2,%3}, [%4];"
                 : "=r"(r[0]), "=r"(r[1]), "=r"(r[2]), "=r"(r[3]) : "r"(addr));
}
__device__ __forceinline__ void mma_bf16(float* c, const uint32_t* a,
                                         uint32_t b0, uint32_t b1) {
    asm volatile(
        "mma.sync.aligned.m16n8k16.row.col.f32.bf16.bf16.f32 "
        "{%0,%1,%2,%3}, {%4,%5,%6,%7}, {%8,%9}, {%0,%1,%2,%3};"
        : "+f"(c[0]), "+f"(c[1]), "+f"(c[2]), "+f"(c[3])
        : "r"(a[0]), "r"(a[1]), "r"(a[2]), "r"(a[3]), "r"(b0), "r"(b1));
}
__device__ __forceinline__ void cp_async16(uint32_t saddr, const void* gaddr) {
    asm volatile("cp.async.ca.shared.global [%0], [%1], 16;"
                 :: "r"(saddr), "l"(gaddr) : "memory");
}
#define CP_COMMIT() asm volatile("cp.async.commit_group;" ::: "memory")
#define CP_WAIT(n)  asm volatile("cp.async.wait_group %0;" :: "n"(n) : "memory")

// hi/lo split of 4 floats into packed bf16x2 pairs
__device__ __forceinline__ void split4(const float4& v, uint2& hi, uint2& lo) {
    float s[4] = {v.x, v.y, v.z, v.w};
    __nv_bfloat16 h[4], l[4];
#pragma unroll
    for (int j = 0; j < 4; j++) {
        h[j] = __float2bfloat16(s[j]);
        l[j] = __float2bfloat16(s[j] - __bfloat162float(h[j]));
    }
    __nv_bfloat162 h01 = __halves2bfloat162(h[0], h[1]);
    __nv_bfloat162 h23 = __halves2bfloat162(h[2], h[3]);
    __nv_bfloat162 l01 = __halves2bfloat162(l[0], l[1]);
    __nv_bfloat162 l23 = __halves2bfloat162(l[2], l[3]);
    hi = make_uint2(*(uint32_t*)&h01, *(uint32_t*)&h23);
    lo = make_uint2(*(uint32_t*)&l01, *(uint32_t*)&l23);
}

// ---- fast grid barrier: red-arrive + spin on monotonic counter ---------------
__device__ __forceinline__ void grid_barrier(unsigned& target) {
    __syncthreads();
    if (threadIdx.x == 0) {
        __threadfence();
        asm volatile("red.global.gpu.add.u32 [%0], 1;"
                     :: "l"(&g_count) : "memory");
        target += GRID;
        unsigned v;
        do {
            asm volatile("ld.acquire.gpu.u32 %0, [%1];" : "=r"(v) : "l"(&g_count));
        } while ((int)(v - target) < 0);
        __threadfence();
    }
    __syncthreads();
}

__global__ void init_kernel() { g_count = 0u; }

extern __shared__ float smem[];

// -----------------------------------------------------------------------------
// Persistent tensor-core scan (R8 config, proven 8.6us/step): GRID=128.
// CTA (nb, kb): resident bf16 hi/lo of W_hh[kb*128:+128, nb*256:+256] in SMEM.
// -----------------------------------------------------------------------------
#define BP 264      // bf16 per W smem row (528 B; 528 % 128 == 16, conflict-free)
#define AP 136      // bf16 per h smem row
#define SB_HI 0
#define SB_LO (SB_HI + KSL * BP * 2)          // 67584
#define SA_HI (SB_LO + KSL * BP * 2)          // 135168
#define SA_LO (SA_HI + BB * AP * 2)           // 152576
#define SC_SMEM (SA_LO + BB * AP * 2)         // 169984 bytes

__global__ void __launch_bounds__(SCTHREADS) scan_kernel(
    const float* __restrict__ state,
    const float* __restrict__ W,
    float* __restrict__ out)
{
    char* sm = (char*)smem;
    __nv_bfloat16* sbh = (__nv_bfloat16*)(sm + SB_HI);
    __nv_bfloat16* sbl = (__nv_bfloat16*)(sm + SB_LO);
    __nv_bfloat16* sah = (__nv_bfloat16*)(sm + SA_HI);
    __nv_bfloat16* sal = (__nv_bfloat16*)(sm + SA_LO);

    const int tid = threadIdx.x;
    const int cta = blockIdx.x;
    const int nb = cta & (NBD - 1);
    const int kb = cta >> 3;
    const int nbase = nb * NSL;
    const int k0 = kb * KSL;
    const int wid = tid >> 5;
    const int lane = tid & 31;
    const int wn = wid * 32;          // warp's 32-col n slice
    const int lrow = lane & 15;
    const int lcolq = lane >> 4;      // 0 or 1

    const uint32_t sbh_b = smem_to_u32(sbh);
    const uint32_t sbl_b = smem_to_u32(sbl);
    const uint32_t sah_b = smem_to_u32(sah);
    const uint32_t sal_b = smem_to_u32(sal);

    // ---- load + split resident W slice [128k x 256n] (once) ----
#pragma unroll
    for (int i = 0; i < 32; i++) {
        int idx = i * SCTHREADS + tid;      // 0..8191 float4
        int k = idx >> 6;
        int n4 = (idx & 63) * 4;
        float4 w = *(const float4*)&W[(size_t)(k0 + k) * HH + nbase + n4];
        uint2 hi, lo;
        split4(w, hi, lo);
        *(uint2*)&sbh[k * BP + n4] = hi;
        *(uint2*)&sbl[k * BP + n4] = lo;
    }
    __syncthreads();

    unsigned target = 0;

    // epilogue mapping: 128*256 threads == 32768 float4 slots exactly
    const int g = cta * SCTHREADS + tid;
    const int em = g >> 9;
    const int ec4 = (g & 511) * 4;
    const size_t eoff = (size_t)em * HH + ec4;

    for (int t = 0; t < TT; t++) {
        const float* hp = (t == 0) ? state : (out + (size_t)(t - 1) * STEP_ELEMS);

        // ---- stage h slice [64m x 128k] -> bf16 hi/lo SMEM ----
#pragma unroll
        for (int i = 0; i < 8; i++) {
            int idx = i * SCTHREADS + tid;  // 0..2047 float4
            int m = idx >> 5;
            int k4 = (idx & 31) * 4;
            float4 h = __ldcg((const float4*)&hp[(size_t)m * HH + k0 + k4]);
            uint2 hi, lo;
            split4(h, hi, lo);
            *(uint2*)&sah[m * AP + k4] = hi;
            *(uint2*)&sal[m * AP + k4] = lo;
        }
        __syncthreads();

        // ---- mma mainloop: 8 k16 steps over the 128k slice ----
        float c[4][4][4];
#pragma unroll
        for (int mi = 0; mi < 4; mi++)
#pragma unroll
            for (int j = 0; j < 4; j++)
#pragma unroll
                for (int q = 0; q < 4; q++) c[mi][j][q] = 0.0f;

#pragma unroll
        for (int ks = 0; ks < 8; ks++) {
            uint32_t ah[4][4], al[4][4];
#pragma unroll
            for (int mi = 0; mi < 4; mi++) {
                uint32_t off = (uint32_t)((mi * 16 + lrow) * AP +
                                          ks * 16 + lcolq * 8) * 2;
                ldsm_x4(sah_b + off, ah[mi]);
                ldsm_x4(sal_b + off, al[mi]);
            }
            uint32_t bh[2][4], bl[2][4];
#pragma unroll
            for (int np = 0; np < 2; np++) {
                uint32_t off = (uint32_t)((ks * 16 + lrow) * BP +
                                          wn + np * 16 + lcolq * 8) * 2;
                ldsm_x4_t(sbh_b + off, bh[np]);
                ldsm_x4_t(sbl_b + off, bl[np]);
            }
#pragma unroll
            for (int mi = 0; mi < 4; mi++) {
#pragma unroll
                for (int j = 0; j < 4; j++) {
                    const int np = j >> 1, pr = (j & 1) * 2;
                    mma_bf16(c[mi][j], ah[mi], bh[np][pr], bh[np][pr + 1]);
                    mma_bf16(c[mi][j], ah[mi], bl[np][pr], bl[np][pr + 1]);
                    mma_bf16(c[mi][j], al[mi], bh[np][pr], bh[np][pr + 1]);
                }
            }
        }

        // ---- write partial [64 x 256] to g_part[kb] ----
        float* P = g_part + (size_t)kb * STEP_ELEMS;
#pragma unroll
        for (int mi = 0; mi < 4; mi++) {
            const int row0 = mi * 16 + (lane >> 2);
#pragma unroll
            for (int j = 0; j < 4; j++) {
                const int col = nbase + wn + j * 8 + (lane & 3) * 2;
                *(float2*)&P[(size_t)row0 * HH + col] =
                    make_float2(c[mi][j][0], c[mi][j][1]);
                *(float2*)&P[(size_t)(row0 + 8) * HH + col] =
                    make_float2(c[mi][j][2], c[mi][j][3]);
            }
        }
        grid_barrier(target);

        // ---- distributed epilogue: reduce 16 partials + xproj, tanh ----
        {
            float4 s = __ldcg((const float4*)&g_part[eoff]);
#pragma unroll
            for (int k2 = 1; k2 < KBD; k2++) {
                float4 p = __ldcg((const float4*)&g_part[(size_t)k2 * STEP_ELEMS + eoff]);
                s.x += p.x; s.y += p.y; s.z += p.z; s.w += p.w;
            }
            const float4 xv = *(const float4*)&g_xproj[(size_t)t * STEP_ELEMS + eoff];
            float4 r;
            r.x = tanhf(s.x + xv.x);
            r.y = tanhf(s.y + xv.y);
            r.z = tanhf(s.z + xv.z);
            r.w = tanhf(s.w + xv.w);
            *(float4*)&out[(size_t)t * STEP_ELEMS + eoff] = r;
            if (t == TT - 1)
                *(float4*)&out[(size_t)TT * STEP_ELEMS + eoff] = r;   // final_state
        }
        grid_barrier(target);
    }
}

// -----------------------------------------------------------------------------
// Elementwise bf16 hi/lo split: hi = bf16(x), lo = bf16(x - hi)
// -----------------------------------------------------------------------------
__global__ void __launch_bounds__(256) convert_split(
    const float* __restrict__ src,
    __nv_bfloat16* __restrict__ hi,
    __nv_bfloat16* __restrict__ lo)
{
    const int i = blockIdx.x * 256 + threadIdx.x;
    float4 v = ((const float4*)src)[i];
    uint2 h, l;
    split4(v, h, l);
    ((uint2*)hi)[i] = h;
    ((uint2*)lo)[i] = l;
}

// -----------------------------------------------------------------------------
// x_proj via mma.sync bf16-split, cp.async double-buffered, 2 CTAs/SM.
// CTA tile [128m x 128n], 8 warps (2m x 4n), warp 64x32, k-chunk 32.
// smem layout (bf16 elems): A(v,st) at (v*2+st)*XA_SZ; B(v,st) after all A.
// -----------------------------------------------------------------------------
#define XAPAD 40     // bf16 per A smem row (80 B, conflict-free ldmatrix)
#define XBPAD 136    // bf16 per B smem row (272 B, conflict-free ldmatrix)
#define XA_SZ (128 * XAPAD)                  // 5120 bf16
#define XB_SZ (32 * XBPAD)                   // 4352 bf16
#define XB_BASE (4 * XA_SZ)                  // 20480 bf16
#define XP_SMEM ((XB_BASE + 4 * XB_SZ) * 2)  // 75776 bytes

__global__ void __launch_bounds__(256, 2) xproj_mma(
    const __nv_bfloat16* __restrict__ Xhi,
    const __nv_bfloat16* __restrict__ Xlo,
    const __nv_bfloat16* __restrict__ Whi,
    const __nv_bfloat16* __restrict__ Wlo,
    const float* __restrict__ bias)
{
    const uint32_t sb = smem_to_u32(smem);
    const int tid = threadIdx.x;
    const int wid = tid >> 5;
    const int lane = tid & 31;
    const int nbase = blockIdx.x * 128;
    const int mbase = blockIdx.y * 128;
    const int wm = (wid & 1) * 64;
    const int wn = (wid >> 1) * 32;
    const int lrow = lane & 15;
    const int lcolq = lane >> 4;

    const __nv_bfloat16* Xs[2] = {Xhi, Xlo};
    const __nv_bfloat16* Ws[2] = {Whi, Wlo};

    // staging indices (fixed per thread)
    const int ar = tid >> 1;             // A row 0..127
    const int ac8 = (tid & 1) * 16;      // two uint4 per row half: cols 0/16 base
    const int bkr = tid >> 4;            // B k-row 0..15 (x2 halves)
    const int bn8 = (tid & 15) * 8;      // B col group

    float c[4][4][4];
#pragma unroll
    for (int mi = 0; mi < 4; mi++)
#pragma unroll
        for (int j = 0; j < 4; j++)
#pragma unroll
            for (int q = 0; q < 4; q++) c[mi][j][q] = 0.0f;

    // issue cp.async loads for k-chunk ch into stage ch&1
    auto load_chunk = [&](int ch) {
        const int st = ch & 1;
        const int kc = ch * 32;
#pragma unroll
        for (int v = 0; v < 2; v++) {
            // A: 128 rows x 32 bf16 = 512 uint4; thread does rows ar, cols ac8, ac8+8
            uint32_t a_s = sb + (uint32_t)((v * 2 + st) * XA_SZ + ar * XAPAD) * 2;
            const __nv_bfloat16* a_g = &Xs[v][(size_t)(mbase + ar) * DD + kc];
            cp_async16(a_s + ac8 * 2, a_g + ac8);
            cp_async16(a_s + (ac8 + 8) * 2, a_g + ac8 + 8);
            // B: 32 rows x 128 bf16 = 512 uint4; thread does rows bkr, bkr+16
            uint32_t b_s = sb + (uint32_t)(XB_BASE + (v * 2 + st) * XB_SZ) * 2;
            cp_async16(b_s + (uint32_t)(bkr * XBPAD + bn8) * 2,
                       &Ws[v][(size_t)(kc + bkr) * HH + nbase + bn8]);
            cp_async16(b_s + (uint32_t)((bkr + 16) * XBPAD + bn8) * 2,
                       &Ws[v][(size_t)(kc + bkr + 16) * HH + nbase + bn8]);
        }
        CP_COMMIT();
    };

    load_chunk(0);
    load_chunk(1);

    for (int ch = 0; ch < DD / 32; ch++) {       // 32 chunks of k=32
        if (ch == DD / 32 - 1) CP_WAIT(0); else CP_WAIT(1);
        __syncthreads();

        const int st = ch & 1;
        const uint32_t ah_b = sb + (uint32_t)((0 + st) * XA_SZ) * 2;
        const uint32_t al_b = sb + (uint32_t)((2 + st) * XA_SZ) * 2;
        const uint32_t bh_b = sb + (uint32_t)(XB_BASE + (0 + st) * XB_SZ) * 2;
        const uint32_t bl_b = sb + (uint32_t)(XB_BASE + (2 + st) * XB_SZ) * 2;

#pragma unroll
        for (int ks = 0; ks < 2; ks++) {         // two k16 steps
            uint32_t ah[4][4], al[4][4];
#pragma unroll
            for (int mi = 0; mi < 4; mi++) {
                uint32_t off = (uint32_t)((wm + mi * 16 + lrow) * XAPAD +
                                          ks * 16 + lcolq * 8) * 2;
                ldsm_x4(ah_b + off, ah[mi]);
                ldsm_x4(al_b + off, al[mi]);
            }
            uint32_t bh[2][4], bl[2][4];
#pragma unroll
            for (int np = 0; np < 2; np++) {
                uint32_t off = (uint32_t)((ks * 16 + lrow) * XBPAD +
                                          wn + np * 16 + lcolq * 8) * 2;
                ldsm_x4_t(bh_b + off, bh[np]);
                ldsm_x4_t(bl_b + off, bl[np]);
            }
#pragma unroll
            for (int mi = 0; mi < 4; mi++) {
#pragma unroll
                for (int j = 0; j < 4; j++) {
                    const int np = j >> 1, pr = (j & 1) * 2;
                    mma_bf16(c[mi][j], ah[mi], bh[np][pr], bh[np][pr + 1]);
                    mma_bf16(c[mi][j], ah[mi], bl[np][pr], bl[np][pr + 1]);
                    mma_bf16(c[mi][j], al[mi], bh[np][pr], bh[np][pr + 1]);
                }
            }
        }
        __syncthreads();        // all warps done reading stage st
        if (ch + 2 < DD / 32) load_chunk(ch + 2);
    }

    // epilogue: c[mi][j] -> g_xproj (+bias)
#pragma unroll
    for (int mi = 0; mi < 4; mi++) {
        const int row0 = mbase + wm + mi * 16 + (lane >> 2);
#pragma unroll
        for (int j = 0; j < 4; j++) {
            const int col = nbase + wn + j * 8 + (lane & 3) * 2;
            const float b0 = __ldg(&bias[col]);
            const float b1 = __ldg(&bias[col + 1]);
            float2 v0 = make_float2(c[mi][j][0] + b0, c[mi][j][1] + b1);
            float2 v1 = make_float2(c[mi][j][2] + b0, c[mi][j][3] + b1);
            *(float2*)&g_xproj[(size_t)row0 * HH + col] = v0;
            *(float2*)&g_xproj[(size_t)(row0 + 8) * HH + col] = v1;
        }
    }
}

extern "C" void kernel_launch(void* const* d_in, const int* in_sizes, int n_in,
                              void* d_out, int out_size)
{
    (void)in_sizes; (void)n_in; (void)out_size;
    const float* inputs = (const float*)d_in[0];   // [T,B,D]
    const float* state  = (const float*)d_in[1];   // [B,H]
    const float* W_xh   = (const float*)d_in[2];   // [D,H]
    const float* W_hh   = (const float*)d_in[3];   // [H,H]
    const float* b_h    = (const float*)d_in[4];   // [H]
    float* out = (float*)d_out;   // outputs [T,B,H] then final_state [B,H]

    cudaFuncSetAttribute(scan_kernel, cudaFuncAttributeMaxDynamicSharedMemorySize,
                         SC_SMEM);
    cudaFuncSetAttribute(xproj_mma, cudaFuncAttributeMaxDynamicSharedMemorySize,
                         XP_SMEM);

    __nv_bfloat16 *xhi, *xlo, *whi, *wlo;
    cudaGetSymbolAddress((void**)&xhi, g_xhi);
    cudaGetSymbolAddress((void**)&xlo, g_xlo);
    cudaGetSymbolAddress((void**)&whi, g_whi);
    cudaGetSymbolAddress((void**)&wlo, g_wlo);

    // 0) reset barrier counter (deterministic across graph replays)
    init_kernel<<<1, 1>>>();

    // 1) bf16 hi/lo splits of X and W_xh
    convert_split<<<(TT * BB * DD / 4) / 256, 256>>>(inputs, xhi, xlo);
    convert_split<<<(DD * HH / 4) / 256, 256>>>(W_xh, whi, wlo);

    // 2) x_proj via tensor cores (cp.async double-buffered, 2 CTAs/SM)
    xproj_mma<<<dim3(HH / 128, (TT * BB) / 128), 256, XP_SMEM>>>(
        xhi, xlo, whi, wlo, b_h);

    // 3) persistent tensor-core scan (R8 config)
    scan_kernel<<<GRID, SCTHREADS, SC_SMEM>>>(state, W_hh, out);
}

// round 12
// speedup vs baseline: 1.1232x; 1.0136x over previous
#include <cuda_runtime.h>
#include <cuda_bf16.h>
#include <math.h>
#include <stdint.h>

#define TT 256
#define BB 64
#define DD 1024
#define HH 2048

#define GRID 128
#define SCTHREADS 256
#define NBD 8            // n-blocks (each 256 wide)
#define KBD 16           // k-blocks (each 128 deep)
#define NSL 256
#define KSL 128
#define STEP_ELEMS (BB * HH)   // 131072

typedef unsigned long long ull;

// Scratch (no cudaMalloc allowed)
__device__ __align__(16) float g_xproj[(size_t)TT * BB * HH];     // 128 MB
__device__ __align__(16) float g_part[(size_t)KBD * BB * HH];     // 8 MB
__device__ __align__(16) __nv_bfloat16 g_xhi[(size_t)TT * BB * DD];
__device__ __align__(16) __nv_bfloat16 g_xlo[(size_t)TT * BB * DD];
__device__ __align__(16) __nv_bfloat16 g_whi[(size_t)DD * HH];
__device__ __align__(16) __nv_bfloat16 g_wlo[(size_t)DD * HH];
__device__ __align__(16) __nv_bfloat16 g_hhi[(size_t)BB * HH];    // h(t) hi split
__device__ __align__(16) __nv_bfloat16 g_hlo[(size_t)BB * HH];    // h(t) lo split
__device__ unsigned g_count;     // monotonic arrival counter (zeroed per launch)

__device__ __forceinline__ uint32_t smem_to_u32(const void* p) {
    uint32_t a;
    asm("{ .reg .u64 t; cvta.to.shared.u64 t, %1; cvt.u32.u64 %0, t; }"
        : "=r"(a) : "l"(p));
    return a;
}

// ---- mma.sync / cp.async helpers (sm_80-era PTX, fine at compute_103) --------
__device__ __forceinline__ void ldsm_x4(uint32_t addr, uint32_t* r) {
    asm volatile("ldmatrix.sync.aligned.m8n8.x4.shared.b16 {%0,%1,%2,%3}, [%4];"
                 : "=r"(r[0]), "=r"(r[1]), "=r"(r[2]), "=r"(r[3]) : "r"(addr));
}
__device__ __forceinline__ void ldsm_x4_t(uint32_t addr, uint32_t* r) {
    asm volatile("ldmatrix.sync.aligned.m8n8.x4.trans.shared.b16 {%0,%1,%2,%3}, [%4];"
                 : "=r"(r[0]), "=r"(r[1]), "=r"(r[2]), "=r"(r[3]) : "r"(addr));
}
__device__ __forceinline__ void mma_bf16(float* c, const uint32_t* a,
                                         uint32_t b0, uint32_t b1) {
    asm volatile(
        "mma.sync.aligned.m16n8k16.row.col.f32.bf16.bf16.f32 "
        "{%0,%1,%2,%3}, {%4,%5,%6,%7}, {%8,%9}, {%0,%1,%2,%3};"
        : "+f"(c[0]), "+f"(c[1]), "+f"(c[2]), "+f"(c[3])
        : "r"(a[0]), "r"(a[1]), "r"(a[2]), "r"(a[3]), "r"(b0), "r"(b1));
}
__device__ __forceinline__ void cp_async16(uint32_t saddr, const void* gaddr) {
    asm volatile("cp.async.ca.shared.global [%0], [%1], 16;"
                 :: "r"(saddr), "l"(gaddr) : "memory");
}
#define CP_COMMIT() asm volatile("cp.async.commit_group;" ::: "memory")
#define CP_WAIT(n)  asm volatile("cp.async.wait_group %0;" :: "n"(n) : "memory")

// hi/lo split of 4 floats into packed bf16x2 pairs
__device__ __forceinline__ void split4(const float4& v, uint2& hi, uint2& lo) {
    float s[4] = {v.x, v.y, v.z, v.w};
    __nv_bfloat16 h[4], l[4];
#pragma unroll
    for (int j = 0; j < 4; j++) {
        h[j] = __float2bfloat16(s[j]);
        l[j] = __float2bfloat16(s[j] - __bfloat162float(h[j]));
    }
    __nv_bfloat162 h01 = __halves2bfloat162(h[0], h[1]);
    __nv_bfloat162 h23 = __halves2bfloat162(h[2], h[3]);
    __nv_bfloat162 l01 = __halves2bfloat162(l[0], l[1]);
    __nv_bfloat162 l23 = __halves2bfloat162(l[2], l[3]);
    hi = make_uint2(*(uint32_t*)&h01, *(uint32_t*)&h23);
    lo = make_uint2(*(uint32_t*)&l01, *(uint32_t*)&l23);
}

// ---- fast grid barrier: red-arrive + spin on monotonic counter ---------------
__device__ __forceinline__ void grid_barrier(unsigned& target) {
    __syncthreads();
    if (threadIdx.x == 0) {
        __threadfence();
        asm volatile("red.global.gpu.add.u32 [%0], 1;"
                     :: "l"(&g_count) : "memory");
        target += GRID;
        unsigned v;
        do {
            asm volatile("ld.acquire.gpu.u32 %0, [%1];" : "=r"(v) : "l"(&g_count));
        } while ((int)(v - target) < 0);
        __threadfence();
    }
    __syncthreads();
}

__global__ void init_kernel() { g_count = 0u; }

extern __shared__ float smem[];

// -----------------------------------------------------------------------------
// Persistent tensor-core scan (R8 topology): GRID=128, one CTA per (nb, kb).
// h hi/lo splits are produced by the PREVIOUS step's epilogue (registers ->
// g_hhi/g_hlo), so per-step staging is a pure cp.async bf16 copy.
// -----------------------------------------------------------------------------
#define BP 264      // bf16 per W smem row (528 B; 528 % 128 == 16, conflict-free)
#define AP 136      // bf16 per h smem row
#define SB_HI 0
#define SB_LO (SB_HI + KSL * BP * 2)          // 67584
#define SA_HI (SB_LO + KSL * BP * 2)          // 135168
#define SA_LO (SA_HI + BB * AP * 2)           // 152576
#define SC_SMEM (SA_LO + BB * AP * 2)         // 169984 bytes

__global__ void __launch_bounds__(SCTHREADS) scan_kernel(
    const float* __restrict__ state,
    const float* __restrict__ W,
    float* __restrict__ out)
{
    char* sm = (char*)smem;
    __nv_bfloat16* sbh = (__nv_bfloat16*)(sm + SB_HI);
    __nv_bfloat16* sbl = (__nv_bfloat16*)(sm + SB_LO);
    __nv_bfloat16* sah = (__nv_bfloat16*)(sm + SA_HI);
    __nv_bfloat16* sal = (__nv_bfloat16*)(sm + SA_LO);

    const int tid = threadIdx.x;
    const int cta = blockIdx.x;
    const int nb = cta & (NBD - 1);
    const int kb = cta >> 3;
    const int nbase = nb * NSL;
    const int k0 = kb * KSL;
    const int wid = tid >> 5;
    const int lane = tid & 31;
    const int wn = wid * 32;          // warp's 32-col n slice
    const int lrow = lane & 15;
    const int lcolq = lane >> 4;      // 0 or 1

    const uint32_t sbh_b = smem_to_u32(sbh);
    const uint32_t sbl_b = smem_to_u32(sbl);
    const uint32_t sah_b = smem_to_u32(sah);
    const uint32_t sal_b = smem_to_u32(sal);

    // ---- load + split resident W slice [128k x 256n] (once) ----
#pragma unroll
    for (int i = 0; i < 32; i++) {
        int idx = i * SCTHREADS + tid;      // 0..8191 float4
        int k = idx >> 6;
        int n4 = (idx & 63) * 4;
        float4 w = *(const float4*)&W[(size_t)(k0 + k) * HH + nbase + n4];
        uint2 hi, lo;
        split4(w, hi, lo);
        *(uint2*)&sbh[k * BP + n4] = hi;
        *(uint2*)&sbl[k * BP + n4] = lo;
    }
    __syncthreads();

    unsigned target = 0;

    // epilogue mapping: 128*256 threads == 32768 float4 slots exactly
    const int g = cta * SCTHREADS + tid;
    const int em = g >> 9;
    const int ec4 = (g & 511) * 4;
    const size_t eoff = (size_t)em * HH + ec4;

    for (int t = 0; t < TT; t++) {
        // ---- stage h slice [64m x 128k] -> bf16 hi/lo SMEM ----
        if (t == 0) {
            // fp32 state + in-place split (first step only)
#pragma unroll
            for (int i = 0; i < 8; i++) {
                int idx = i * SCTHREADS + tid;  // 0..2047 float4
                int m = idx >> 5;
                int k4 = (idx & 31) * 4;
                float4 h = __ldcg((const float4*)&state[(size_t)m * HH + k0 + k4]);
                uint2 hi, lo;
                split4(h, hi, lo);
                *(uint2*)&sah[m * AP + k4] = hi;
                *(uint2*)&sal[m * AP + k4] = lo;
            }
        } else {
            // pre-split bf16 from previous epilogue: straight cp.async copy
#pragma unroll
            for (int i = 0; i < 4; i++) {
                int idx = i * SCTHREADS + tid;  // 0..1023 chunks of 8 bf16
                int m = idx >> 4;
                int c8 = (idx & 15) * 8;
                size_t goff = (size_t)m * HH + k0 + c8;
                uint32_t soff = (uint32_t)(m * AP + c8) * 2;
                cp_async16(sah_b + soff, &g_hhi[goff]);
                cp_async16(sal_b + soff, &g_hlo[goff]);
            }
            CP_COMMIT();
            CP_WAIT(0);
        }
        __syncthreads();

        // ---- mma mainloop: 8 k16 steps over the 128k slice ----
        float c[4][4][4];
#pragma unroll
        for (int mi = 0; mi < 4; mi++)
#pragma unroll
            for (int j = 0; j < 4; j++)
#pragma unroll
                for (int q = 0; q < 4; q++) c[mi][j][q] = 0.0f;

#pragma unroll
        for (int ks = 0; ks < 8; ks++) {
            uint32_t ah[4][4], al[4][4];
#pragma unroll
            for (int mi = 0; mi < 4; mi++) {
                uint32_t off = (uint32_t)((mi * 16 + lrow) * AP +
                                          ks * 16 + lcolq * 8) * 2;
                ldsm_x4(sah_b + off, ah[mi]);
                ldsm_x4(sal_b + off, al[mi]);
            }
            uint32_t bh[2][4], bl[2][4];
#pragma unroll
            for (int np = 0; np < 2; np++) {
                uint32_t off = (uint32_t)((ks * 16 + lrow) * BP +
                                          wn + np * 16 + lcolq * 8) * 2;
                ldsm_x4_t(sbh_b + off, bh[np]);
                ldsm_x4_t(sbl_b + off, bl[np]);
            }
#pragma unroll
            for (int mi = 0; mi < 4; mi++) {
#pragma unroll
                for (int j = 0; j < 4; j++) {
                    const int np = j >> 1, pr = (j & 1) * 2;
                    mma_bf16(c[mi][j], ah[mi], bh[np][pr], bh[np][pr + 1]);
                    mma_bf16(c[mi][j], ah[mi], bl[np][pr], bl[np][pr + 1]);
                    mma_bf16(c[mi][j], al[mi], bh[np][pr], bh[np][pr + 1]);
                }
            }
        }

        // ---- write partial [64 x 256] to g_part[kb] ----
        float* P = g_part + (size_t)kb * STEP_ELEMS;
#pragma unroll
        for (int mi = 0; mi < 4; mi++) {
            const int row0 = mi * 16 + (lane >> 2);
#pragma unroll
            for (int j = 0; j < 4; j++) {
                const int col = nbase + wn + j * 8 + (lane & 3) * 2;
                *(float2*)&P[(size_t)row0 * HH + col] =
                    make_float2(c[mi][j][0], c[mi][j][1]);
                *(float2*)&P[(size_t)(row0 + 8) * HH + col] =
                    make_float2(c[mi][j][2], c[mi][j][3]);
            }
        }
        grid_barrier(target);

        // ---- distributed epilogue: reduce 16 partials + xproj, tanh,
        //      write fp32 out[t] AND bf16 hi/lo for the next step's staging ----
        {
            float4 s = __ldcg((const float4*)&g_part[eoff]);
#pragma unroll
            for (int k2 = 1; k2 < KBD; k2++) {
                float4 p = __ldcg((const float4*)&g_part[(size_t)k2 * STEP_ELEMS + eoff]);
                s.x += p.x; s.y += p.y; s.z += p.z; s.w += p.w;
            }
            const float4 xv = *(const float4*)&g_xproj[(size_t)t * STEP_ELEMS + eoff];
            float4 r;
            r.x = tanhf(s.x + xv.x);
            r.y = tanhf(s.y + xv.y);
            r.z = tanhf(s.z + xv.z);
            r.w = tanhf(s.w + xv.w);
            *(float4*)&out[(size_t)t * STEP_ELEMS + eoff] = r;
            uint2 hi, lo;
            split4(r, hi, lo);
            *(uint2*)&g_hhi[eoff] = hi;
            *(uint2*)&g_hlo[eoff] = lo;
            if (t == TT - 1)
                *(float4*)&out[(size_t)TT * STEP_ELEMS + eoff] = r;   // final_state
        }
        grid_barrier(target);
    }
}

// -----------------------------------------------------------------------------
// Elementwise bf16 hi/lo split: hi = bf16(x), lo = bf16(x - hi)
// -----------------------------------------------------------------------------
__global__ void __launch_bounds__(256) convert_split(
    const float* __restrict__ src,
    __nv_bfloat16* __restrict__ hi,
    __nv_bfloat16* __restrict__ lo)
{
    const int i = blockIdx.x * 256 + threadIdx.x;
    float4 v = ((const float4*)src)[i];
    uint2 h, l;
    split4(v, h, l);
    ((uint2*)hi)[i] = h;
    ((uint2*)lo)[i] = l;
}

// -----------------------------------------------------------------------------
// x_proj via mma.sync bf16-split, cp.async double-buffered, 2 CTAs/SM
// (validated R10 kernel, unchanged)
// -----------------------------------------------------------------------------
#define XAPAD 40     // bf16 per A smem row (80 B, conflict-free ldmatrix)
#define XBPAD 136    // bf16 per B smem row (272 B, conflict-free ldmatrix)
#define XA_SZ (128 * XAPAD)                  // 5120 bf16
#define XB_SZ (32 * XBPAD)                   // 4352 bf16
#define XB_BASE (4 * XA_SZ)                  // 20480 bf16
#define XP_SMEM ((XB_BASE + 4 * XB_SZ) * 2)  // 75776 bytes

__global__ void __launch_bounds__(256, 2) xproj_mma(
    const __nv_bfloat16* __restrict__ Xhi,
    const __nv_bfloat16* __restrict__ Xlo,
    const __nv_bfloat16* __restrict__ Whi,
    const __nv_bfloat16* __restrict__ Wlo,
    const float* __restrict__ bias)
{
    const uint32_t sb = smem_to_u32(smem);
    const int tid = threadIdx.x;
    const int wid = tid >> 5;
    const int lane = tid & 31;
    const int nbase = blockIdx.x * 128;
    const int mbase = blockIdx.y * 128;
    const int wm = (wid & 1) * 64;
    const int wn = (wid >> 1) * 32;
    const int lrow = lane & 15;
    const int lcolq = lane >> 4;

    const __nv_bfloat16* Xs[2] = {Xhi, Xlo};
    const __nv_bfloat16* Ws[2] = {Whi, Wlo};

    const int ar = tid >> 1;
    const int ac8 = (tid & 1) * 16;
    const int bkr = tid >> 4;
    const int bn8 = (tid & 15) * 8;

    float c[4][4][4];
#pragma unroll
    for (int mi = 0; mi < 4; mi++)
#pragma unroll
        for (int j = 0; j < 4; j++)
#pragma unroll
            for (int q = 0; q < 4; q++) c[mi][j][q] = 0.0f;

    auto load_chunk = [&](int ch) {
        const int st = ch & 1;
        const int kc = ch * 32;
#pragma unroll
        for (int v = 0; v < 2; v++) {
            uint32_t a_s = sb + (uint32_t)((v * 2 + st) * XA_SZ + ar * XAPAD) * 2;
            const __nv_bfloat16* a_g = &Xs[v][(size_t)(mbase + ar) * DD + kc];
            cp_async16(a_s + ac8 * 2, a_g + ac8);
            cp_async16(a_s + (ac8 + 8) * 2, a_g + ac8 + 8);
            uint32_t b_s = sb + (uint32_t)(XB_BASE + (v * 2 + st) * XB_SZ) * 2;
            cp_async16(b_s + (uint32_t)(bkr * XBPAD + bn8) * 2,
                       &Ws[v][(size_t)(kc + bkr) * HH + nbase + bn8]);
            cp_async16(b_s + (uint32_t)((bkr + 16) * XBPAD + bn8) * 2,
                       &Ws[v][(size_t)(kc + bkr + 16) * HH + nbase + bn8]);
        }
        CP_COMMIT();
    };

    load_chunk(0);
    load_chunk(1);

    for (int ch = 0; ch < DD / 32; ch++) {
        if (ch == DD / 32 - 1) CP_WAIT(0); else CP_WAIT(1);
        __syncthreads();

        const int st = ch & 1;
        const uint32_t ah_b = sb + (uint32_t)((0 + st) * XA_SZ) * 2;
        const uint32_t al_b = sb + (uint32_t)((2 + st) * XA_SZ) * 2;
        const uint32_t bh_b = sb + (uint32_t)(XB_BASE + (0 + st) * XB_SZ) * 2;
        const uint32_t bl_b = sb + (uint32_t)(XB_BASE + (2 + st) * XB_SZ) * 2;

#pragma unroll
        for (int ks = 0; ks < 2; ks++) {
            uint32_t ah[4][4], al[4][4];
#pragma unroll
            for (int mi = 0; mi < 4; mi++) {
                uint32_t off = (uint32_t)((wm + mi * 16 + lrow) * XAPAD +
                                          ks * 16 + lcolq * 8) * 2;
                ldsm_x4(ah_b + off, ah[mi]);
                ldsm_x4(al_b + off, al[mi]);
            }
            uint32_t bh[2][4], bl[2][4];
#pragma unroll
            for (int np = 0; np < 2; np++) {
                uint32_t off = (uint32_t)((ks * 16 + lrow) * XBPAD +
                                          wn + np * 16 + lcolq * 8) * 2;
                ldsm_x4_t(bh_b + off, bh[np]);
                ldsm_x4_t(bl_b + off, bl[np]);
            }
#pragma unroll
            for (int mi = 0; mi < 4; mi++) {
#pragma unroll
                for (int j = 0; j < 4; j++) {
                    const int np = j >> 1, pr = (j & 1) * 2;
                    mma_bf16(c[mi][j], ah[mi], bh[np][pr], bh[np][pr + 1]);
                    mma_bf16(c[mi][j], ah[mi], bl[np][pr], bl[np][pr + 1]);
                    mma_bf16(c[mi][j], al[mi], bh[np][pr], bh[np][pr + 1]);
                }
            }
        }
        __syncthreads();
        if (ch + 2 < DD / 32) load_chunk(ch + 2);
    }

#pragma unroll
    for (int mi = 0; mi < 4; mi++) {
        const int row0 = mbase + wm + mi * 16 + (lane >> 2);
#pragma unroll
        for (int j = 0; j < 4; j++) {
            const int col = nbase + wn + j * 8 + (lane & 3) * 2;
            const float b0 = __ldg(&bias[col]);
            const float b1 = __ldg(&bias[col + 1]);
            float2 v0 = make_float2(c[mi][j][0] + b0, c[mi][j][1] + b1);
            float2 v1 = make_float2(c[mi][j][2] + b0, c[mi][j][3] + b1);
            *(float2*)&g_xproj[(size_t)row0 * HH + col] = v0;
            *(float2*)&g_xproj[(size_t)(row0 + 8) * HH + col] = v1;
        }
    }
}

extern "C" void kernel_launch(void* const* d_in, const int* in_sizes, int n_in,
                              void* d_out, int out_size)
{
    (void)in_sizes; (void)n_in; (void)out_size;
    const float* inputs = (const float*)d_in[0];   // [T,B,D]
    const float* state  = (const float*)d_in[1];   // [B,H]
    const float* W_xh   = (const float*)d_in[2];   // [D,H]
    const float* W_hh   = (const float*)d_in[3];   // [H,H]
    const float* b_h    = (const float*)d_in[4];   // [H]
    float* out = (float*)d_out;   // outputs [T,B,H] then final_state [B,H]

    cudaFuncSetAttribute(scan_kernel, cudaFuncAttributeMaxDynamicSharedMemorySize,
                         SC_SMEM);
    cudaFuncSetAttribute(xproj_mma, cudaFuncAttributeMaxDynamicSharedMemorySize,
                         XP_SMEM);

    __nv_bfloat16 *xhi, *xlo, *whi, *wlo;
    cudaGetSymbolAddress((void**)&xhi, g_xhi);
    cudaGetSymbolAddress((void**)&xlo, g_xlo);
    cudaGetSymbolAddress((void**)&whi, g_whi);
    cudaGetSymbolAddress((void**)&wlo, g_wlo);

    // 0) reset barrier counter (deterministic across graph replays)
    init_kernel<<<1, 1>>>();

    // 1) bf16 hi/lo splits of X and W_xh
    convert_split<<<(TT * BB * DD / 4) / 256, 256>>>(inputs, xhi, xlo);
    convert_split<<<(DD * HH / 4) / 256, 256>>>(W_xh, whi, wlo);

    // 2) x_proj via tensor cores (cp.async double-buffered, 2 CTAs/SM)
    xproj_mma<<<dim3(HH / 128, (TT * BB) / 128), 256, XP_SMEM>>>(
        xhi, xlo, whi, wlo, b_h);

    // 3) persistent tensor-core scan (R8 topology, epilogue-split h staging)
    scan_kernel<<<GRID, SCTHREADS, SC_SMEM>>>(state, W_hh, out);
}